// round 1
// baseline (speedup 1.0000x reference)
#include <cuda_runtime.h>

#define Nn   4096
#define Bb   4
#define Kk   8
#define TPB  128
#define NBLK ((Nn / TPB) * Bb)   // 128 blocks
#define EPSF 1e-12f

__device__ float g_partials[3 * NBLK];

// Scan all Nn candidates in smem, keep 9 smallest squared distances (ascending,
// ties -> lower index first, matching lax.top_k stability with monotonic j).
__device__ __forceinline__ void scan9(const float4* __restrict__ s,
                                      float px, float py, float pz, float sq,
                                      float bd[9], int bi[9]) {
#pragma unroll
    for (int t = 0; t < 9; t++) { bd[t] = 3.4e38f; bi[t] = 0; }
    float m2x = -2.0f * px, m2y = -2.0f * py, m2z = -2.0f * pz;
#pragma unroll 4
    for (int j = 0; j < Nn; j++) {
        float4 q  = s[j];
        float base = sq + q.w;
        float d2 = fmaf(m2x, q.x, fmaf(m2y, q.y, fmaf(m2z, q.z, base)));
        if (d2 < bd[8]) {
            float v = d2; int vi = j;
#pragma unroll
            for (int t = 0; t < 9; t++) {
                bool c = v < bd[t];
                float od = bd[t]; int oi = bi[t];
                bd[t] = c ? v  : od;
                bi[t] = c ? vi : oi;
                v  = c ? od : v;
                vi = c ? oi : vi;
            }
        }
    }
}

__global__ void __launch_bounds__(TPB)
knn_loss_kernel(const float* __restrict__ pred, const float* __restrict__ target) {
    extern __shared__ float4 smem[];
    float4* sp = smem;        // pred points of this batch  (x,y,z,|x|^2)
    float4* st = smem + Nn;   // target points of this batch

    const int tid = threadIdx.x;
    const int b   = blockIdx.y;

    const float* pb = pred   + (size_t)b * Nn * 3;
    const float* tb = target + (size_t)b * Nn * 3;
    for (int p = tid; p < Nn; p += TPB) {
        float x = pb[3*p+0], y = pb[3*p+1], z = pb[3*p+2];
        sp[p] = make_float4(x, y, z, fmaf(x, x, fmaf(y, y, z*z)));
        float a = tb[3*p+0], c = tb[3*p+1], d = tb[3*p+2];
        st[p] = make_float4(a, c, d, fmaf(a, a, fmaf(c, c, d*d)));
    }
    __syncthreads();

    const int i = blockIdx.x * TPB + tid;
    const float4 Pi = sp[i];
    const float4 Ti = st[i];

    float bd[9]; int bi[9];

    // ---- pred kNN ----
    scan9(sp, Pi.x, Pi.y, Pi.z, Pi.w, bd, bi);

    float pnx[Kk], pny[Kk], pnz[Kk];              // normalized pred vecs
    float pxx = 0.f, pyy = 0.f, pzz = 0.f, pxy = 0.f, pxz = 0.f, pyz = 0.f;
    float pdens = 0.f;
#pragma unroll
    for (int k = 0; k < Kk; k++) {
        pdens += sqrtf(fmaxf(bd[k+1], EPSF));     // neighbor distance (clamped)
        float4 q = sp[bi[k+1]];
        float vx = q.x - Pi.x, vy = q.y - Pi.y, vz = q.z - Pi.z;
        pxx = fmaf(vx, vx, pxx); pyy = fmaf(vy, vy, pyy); pzz = fmaf(vz, vz, pzz);
        pxy = fmaf(vx, vy, pxy); pxz = fmaf(vx, vz, pxz); pyz = fmaf(vy, vz, pyz);
        float nrm = sqrtf(fmaf(vx, vx, fmaf(vy, vy, vz * vz)));
        float inv = 1.0f / fmaxf(nrm, EPSF);
        pnx[k] = vx * inv; pny[k] = vy * inv; pnz[k] = vz * inv;
    }
    pdens *= 0.125f;
    pxx *= 0.125f; pyy *= 0.125f; pzz *= 0.125f;
    pxy *= 0.125f; pxz *= 0.125f; pyz *= 0.125f;

    // ---- target kNN ----
    scan9(st, Ti.x, Ti.y, Ti.z, Ti.w, bd, bi);

    float txx = 0.f, tyy = 0.f, tzz = 0.f, txy = 0.f, txz = 0.f, tyz = 0.f;
    float tdens = 0.f, dsum = 0.f;
#pragma unroll
    for (int k = 0; k < Kk; k++) {
        tdens += sqrtf(fmaxf(bd[k+1], EPSF));
        float4 q = st[bi[k+1]];
        float vx = q.x - Ti.x, vy = q.y - Ti.y, vz = q.z - Ti.z;
        txx = fmaf(vx, vx, txx); tyy = fmaf(vy, vy, tyy); tzz = fmaf(vz, vz, tzz);
        txy = fmaf(vx, vy, txy); txz = fmaf(vx, vz, txz); tyz = fmaf(vy, vz, tyz);
        float nrm = sqrtf(fmaf(vx, vx, fmaf(vy, vy, vz * vz)));
        float inv = 1.0f / fmaxf(nrm, EPSF);
        dsum = fmaf(pnx[k], vx * inv, dsum);
        dsum = fmaf(pny[k], vy * inv, dsum);
        dsum = fmaf(pnz[k], vz * inv, dsum);
    }
    tdens *= 0.125f;
    txx *= 0.125f; tyy *= 0.125f; tzz *= 0.125f;
    txy *= 0.125f; txz *= 0.125f; tyz *= 0.125f;

    float dd = pdens - tdens;
    float c_den = dd * dd;
    float exx = pxx - txx, eyy = pyy - tyy, ezz = pzz - tzz;
    float exy = pxy - txy, exz = pxz - txz, eyz = pyz - tyz;
    float fro = exx*exx + eyy*eyy + ezz*ezz + 2.0f*(exy*exy + exz*exz + eyz*eyz);
    float c_cur = sqrtf(fro);

    // ---- block reduction (reuse smem after all gathers complete) ----
    __syncthreads();
    float* red = (float*)smem;
    red[tid]          = c_den;
    red[TPB + tid]    = dsum;
    red[2*TPB + tid]  = c_cur;
    __syncthreads();
#pragma unroll
    for (int s = TPB / 2; s > 0; s >>= 1) {
        if (tid < s) {
            red[tid]         += red[tid + s];
            red[TPB + tid]   += red[TPB + tid + s];
            red[2*TPB + tid] += red[2*TPB + tid + s];
        }
        __syncthreads();
    }
    if (tid == 0) {
        int blk = blockIdx.y * gridDim.x + blockIdx.x;
        g_partials[blk]           = red[0];
        g_partials[NBLK + blk]    = red[TPB];
        g_partials[2*NBLK + blk]  = red[2*TPB];
    }
}

__global__ void __launch_bounds__(NBLK) finalize_kernel(float* __restrict__ out) {
    __shared__ float r[3 * NBLK];
    int tid = threadIdx.x;
    r[tid]          = g_partials[tid];
    r[NBLK + tid]   = g_partials[NBLK + tid];
    r[2*NBLK + tid] = g_partials[2*NBLK + tid];
    __syncthreads();
#pragma unroll
    for (int s = NBLK / 2; s > 0; s >>= 1) {
        if (tid < s) {
            r[tid]          += r[tid + s];
            r[NBLK + tid]   += r[NBLK + tid + s];
            r[2*NBLK + tid] += r[2*NBLK + tid + s];
        }
        __syncthreads();
    }
    if (tid == 0) {
        const float invBN = 1.0f / (float)(Bb * Nn);
        float density_loss   = r[0] * invBN;
        float direction_loss = 1.0f - r[NBLK] * (invBN / (float)Kk);
        float curvature_loss = r[2*NBLK] * invBN;
        out[0] = density_loss + 0.5f * direction_loss + 0.5f * curvature_loss;
    }
}

extern "C" void kernel_launch(void* const* d_in, const int* in_sizes, int n_in,
                              void* d_out, int out_size) {
    (void)in_sizes; (void)n_in; (void)out_size;
    const float* pred   = (const float*)d_in[0];
    const float* target = (const float*)d_in[1];

    size_t smem_bytes = 2 * Nn * sizeof(float4);   // 128 KB
    cudaFuncSetAttribute(knn_loss_kernel,
                         cudaFuncAttributeMaxDynamicSharedMemorySize,
                         (int)smem_bytes);

    dim3 grid(Nn / TPB, Bb);
    knn_loss_kernel<<<grid, TPB, smem_bytes>>>(pred, target);
    finalize_kernel<<<1, NBLK>>>((float*)d_out);
}

// round 2
// speedup vs baseline: 1.0031x; 1.0031x over previous
#include <cuda_runtime.h>

#define Nn   4096
#define Bb   4
#define Kk   8
#define TPB  128
#define NBLK ((Nn / TPB) * Bb)   // 128 blocks
#define EPSF 1e-12f

__device__ float g_partials[3 * NBLK];

// Scan all Nn candidates in smem, keep 9 smallest squared distances (ascending,
// ties -> lower index first, matching lax.top_k stability with monotonic j).
__device__ __forceinline__ void scan9(const float4* __restrict__ s,
                                      float px, float py, float pz, float sq,
                                      float bd[9], int bi[9]) {
#pragma unroll
    for (int t = 0; t < 9; t++) { bd[t] = 3.4e38f; bi[t] = 0; }
    float m2x = -2.0f * px, m2y = -2.0f * py, m2z = -2.0f * pz;
#pragma unroll 4
    for (int j = 0; j < Nn; j++) {
        float4 q  = s[j];
        float base = sq + q.w;
        float d2 = fmaf(m2x, q.x, fmaf(m2y, q.y, fmaf(m2z, q.z, base)));
        if (d2 < bd[8]) {
            float v = d2; int vi = j;
#pragma unroll
            for (int t = 0; t < 9; t++) {
                bool c = v < bd[t];
                float od = bd[t]; int oi = bi[t];
                bd[t] = c ? v  : od;
                bi[t] = c ? vi : oi;
                v  = c ? od : v;
                vi = c ? oi : vi;
            }
        }
    }
}

__global__ void __launch_bounds__(TPB)
knn_loss_kernel(const float* __restrict__ pred, const float* __restrict__ target) {
    extern __shared__ float4 smem[];
    float4* sp = smem;        // pred points of this batch  (x,y,z,|x|^2)
    float4* st = smem + Nn;   // target points of this batch

    const int tid = threadIdx.x;
    const int b   = blockIdx.y;

    const float* pb = pred   + (size_t)b * Nn * 3;
    const float* tb = target + (size_t)b * Nn * 3;
    for (int p = tid; p < Nn; p += TPB) {
        float x = pb[3*p+0], y = pb[3*p+1], z = pb[3*p+2];
        sp[p] = make_float4(x, y, z, fmaf(x, x, fmaf(y, y, z*z)));
        float a = tb[3*p+0], c = tb[3*p+1], d = tb[3*p+2];
        st[p] = make_float4(a, c, d, fmaf(a, a, fmaf(c, c, d*d)));
    }
    __syncthreads();

    const int i = blockIdx.x * TPB + tid;
    const float4 Pi = sp[i];
    const float4 Ti = st[i];

    float bd[9]; int bi[9];

    // ---- pred kNN ----
    scan9(sp, Pi.x, Pi.y, Pi.z, Pi.w, bd, bi);

    float pnx[Kk], pny[Kk], pnz[Kk];              // normalized pred vecs
    float pxx = 0.f, pyy = 0.f, pzz = 0.f, pxy = 0.f, pxz = 0.f, pyz = 0.f;
    float pdens = 0.f;
#pragma unroll
    for (int k = 0; k < Kk; k++) {
        pdens += sqrtf(fmaxf(bd[k+1], EPSF));     // neighbor distance (clamped)
        float4 q = sp[bi[k+1]];
        float vx = q.x - Pi.x, vy = q.y - Pi.y, vz = q.z - Pi.z;
        pxx = fmaf(vx, vx, pxx); pyy = fmaf(vy, vy, pyy); pzz = fmaf(vz, vz, pzz);
        pxy = fmaf(vx, vy, pxy); pxz = fmaf(vx, vz, pxz); pyz = fmaf(vy, vz, pyz);
        float nrm = sqrtf(fmaf(vx, vx, fmaf(vy, vy, vz * vz)));
        float inv = 1.0f / fmaxf(nrm, EPSF);
        pnx[k] = vx * inv; pny[k] = vy * inv; pnz[k] = vz * inv;
    }
    pdens *= 0.125f;
    pxx *= 0.125f; pyy *= 0.125f; pzz *= 0.125f;
    pxy *= 0.125f; pxz *= 0.125f; pyz *= 0.125f;

    // ---- target kNN ----
    scan9(st, Ti.x, Ti.y, Ti.z, Ti.w, bd, bi);

    float txx = 0.f, tyy = 0.f, tzz = 0.f, txy = 0.f, txz = 0.f, tyz = 0.f;
    float tdens = 0.f, dsum = 0.f;
#pragma unroll
    for (int k = 0; k < Kk; k++) {
        tdens += sqrtf(fmaxf(bd[k+1], EPSF));
        float4 q = st[bi[k+1]];
        float vx = q.x - Ti.x, vy = q.y - Ti.y, vz = q.z - Ti.z;
        txx = fmaf(vx, vx, txx); tyy = fmaf(vy, vy, tyy); tzz = fmaf(vz, vz, tzz);
        txy = fmaf(vx, vy, txy); txz = fmaf(vx, vz, txz); tyz = fmaf(vy, vz, tyz);
        float nrm = sqrtf(fmaf(vx, vx, fmaf(vy, vy, vz * vz)));
        float inv = 1.0f / fmaxf(nrm, EPSF);
        dsum = fmaf(pnx[k], vx * inv, dsum);
        dsum = fmaf(pny[k], vy * inv, dsum);
        dsum = fmaf(pnz[k], vz * inv, dsum);
    }
    tdens *= 0.125f;
    txx *= 0.125f; tyy *= 0.125f; tzz *= 0.125f;
    txy *= 0.125f; txz *= 0.125f; tyz *= 0.125f;

    float dd = pdens - tdens;
    float c_den = dd * dd;
    float exx = pxx - txx, eyy = pyy - tyy, ezz = pzz - tzz;
    float exy = pxy - txy, exz = pxz - txz, eyz = pyz - tyz;
    float fro = exx*exx + eyy*eyy + ezz*ezz + 2.0f*(exy*exy + exz*exz + eyz*eyz);
    float c_cur = sqrtf(fro);

    // ---- block reduction (reuse smem after all gathers complete) ----
    __syncthreads();
    float* red = (float*)smem;
    red[tid]          = c_den;
    red[TPB + tid]    = dsum;
    red[2*TPB + tid]  = c_cur;
    __syncthreads();
#pragma unroll
    for (int s = TPB / 2; s > 0; s >>= 1) {
        if (tid < s) {
            red[tid]         += red[tid + s];
            red[TPB + tid]   += red[TPB + tid + s];
            red[2*TPB + tid] += red[2*TPB + tid + s];
        }
        __syncthreads();
    }
    if (tid == 0) {
        int blk = blockIdx.y * gridDim.x + blockIdx.x;
        g_partials[blk]           = red[0];
        g_partials[NBLK + blk]    = red[TPB];
        g_partials[2*NBLK + blk]  = red[2*TPB];
    }
}

__global__ void __launch_bounds__(NBLK) finalize_kernel(float* __restrict__ out) {
    __shared__ float r[3 * NBLK];
    int tid = threadIdx.x;
    r[tid]          = g_partials[tid];
    r[NBLK + tid]   = g_partials[NBLK + tid];
    r[2*NBLK + tid] = g_partials[2*NBLK + tid];
    __syncthreads();
#pragma unroll
    for (int s = NBLK / 2; s > 0; s >>= 1) {
        if (tid < s) {
            r[tid]          += r[tid + s];
            r[NBLK + tid]   += r[NBLK + tid + s];
            r[2*NBLK + tid] += r[2*NBLK + tid + s];
        }
        __syncthreads();
    }
    if (tid == 0) {
        const float invBN = 1.0f / (float)(Bb * Nn);
        float density_loss   = r[0] * invBN;
        float direction_loss = 1.0f - r[NBLK] * (invBN / (float)Kk);
        float curvature_loss = r[2*NBLK] * invBN;
        out[0] = density_loss + 0.5f * direction_loss + 0.5f * curvature_loss;
    }
}

extern "C" void kernel_launch(void* const* d_in, const int* in_sizes, int n_in,
                              void* d_out, int out_size) {
    (void)in_sizes; (void)n_in; (void)out_size;
    const float* pred   = (const float*)d_in[0];
    const float* target = (const float*)d_in[1];

    size_t smem_bytes = 2 * Nn * sizeof(float4);   // 128 KB
    cudaFuncSetAttribute(knn_loss_kernel,
                         cudaFuncAttributeMaxDynamicSharedMemorySize,
                         (int)smem_bytes);

    dim3 grid(Nn / TPB, Bb);
    knn_loss_kernel<<<grid, TPB, smem_bytes>>>(pred, target);
    finalize_kernel<<<1, NBLK>>>((float*)d_out);
}